// round 10
// baseline (speedup 1.0000x reference)
#include <cuda_runtime.h>

#define N_ELEMS 8192
#define NT 256
#define NBLK1 32                    // kernel-1 blocks (32 x 256 = 8192)
#define NBUCK 20
#define CAP 256                     // per-(bucket,block) segment capacity
#define TH 0.05f
#define SPLITB 14                   // i-splits per bucket in kernel 2
#define NB2 (NBUCK * SPLITB)        // 280 blocks, ~2 per SM
#define JSPLIT 4
#define WCAP 4096
#define MAXSEG 96                   // 3 buckets x 32 segments

// ---- scratch (__device__ globals; no allocation allowed) ----
__device__ float2 g_seg[NBUCK * NBLK1 * CAP];      // interleaved (psi, d)
__device__ int    g_hist[NBUCK * NBLK1];           // [bucket][block]
__device__ float  g_bce[NBLK1], g_sd[NBLK1], g_sd2[NBLK1];
__device__ float  g_psq[NB2];
__device__ int    g_pcnt[NB2];
__device__ unsigned g_done;                        // ticket; self-resets

__device__ __forceinline__ float warp_sum_f(float v) {
#pragma unroll
    for (int o = 16; o > 0; o >>= 1) v += __shfl_down_sync(0xffffffffu, v, o);
    return v;
}
__device__ __forceinline__ int warp_sum_i(int v) {
#pragma unroll
    for (int o = 16; o > 0; o >>= 1) v += __shfl_down_sync(0xffffffffu, v, o);
    return v;
}
__device__ __forceinline__ int bucket_of(float p) {
    int b = (int)(p * 20.0f);
    return b > (NBUCK - 1) ? (NBUCK - 1) : b;
}

// ---------------------------------------------------------------------------
// Kernel 1: prep + deterministic segmented bucket scatter + hist + O(N) sums
// ---------------------------------------------------------------------------
__global__ void __launch_bounds__(NT, 1)
prep_scatter_kernel(const float* __restrict__ pred,
                    const float* __restrict__ psi) {
    __shared__ int   wcnt[NT / 32][NBUCK];
    __shared__ float rf1[NT / 32], rf2[NT / 32], rf3[NT / 32];

    const int tid = threadIdx.x, blk = blockIdx.x;
    const int lane = tid & 31, w = tid >> 5;

    if (tid < (NT / 32) * NBUCK) ((int*)wcnt)[tid] = 0;
    __syncthreads();

    int i = blk * NT + tid;
    float x = pred[i];
    float t = psi[i];

    // stable BCE-with-logits term (fast math, err ~2^-22)
    float term = fmaxf(x, 0.0f) - x * t + __logf(1.0f + __expf(-fabsf(x)));
    // logit with clamp [eps, 1-eps]
    float p = fminf(fmaxf(t, 1e-7f), 1.0f - 1e-7f);
    float d = x - (__logf(p) - __logf(1.0f - p));

    int b = bucket_of(t);
    unsigned m = __match_any_sync(0xffffffffu, b);
    int lr = __popc(m & ((1u << lane) - 1u));
    if (lr == 0) wcnt[w][b] = __popc(m);
    __syncthreads();

    int rank = lr;
#pragma unroll
    for (int ww = 0; ww < NT / 32; ww++)
        if (ww < w) rank += wcnt[ww][b];

    g_seg[(b * NBLK1 + blk) * CAP + rank] = make_float2(t, d);

    if (tid < NBUCK) {
        int s = 0;
#pragma unroll
        for (int ww = 0; ww < NT / 32; ww++) s += wcnt[ww][tid];
        g_hist[tid * NBLK1 + blk] = s;
    }

    float s1 = warp_sum_f(term);
    float s2 = warp_sum_f(d);
    float s3 = warp_sum_f(d * d);
    if (lane == 0) { rf1[w] = s1; rf2[w] = s2; rf3[w] = s3; }
    __syncthreads();
    if (tid == 0) {
        float a1 = 0, a2 = 0, a3 = 0;
#pragma unroll
        for (int ww = 0; ww < NT / 32; ww++) { a1 += rf1[ww]; a2 += rf2[ww]; a3 += rf3[ww]; }
        g_bce[blk] = a1; g_sd[blk] = a2; g_sd2[blk] = a3;
    }
}

// ---------------------------------------------------------------------------
// Kernel 2: gather 3-bucket window -> smem (float2), BRANCHLESS invalid-pair
// scan, last-block-ticket finalize.
// ---------------------------------------------------------------------------
__global__ void __launch_bounds__(NT, 2)
pair_final_kernel(const int* __restrict__ flag, float* __restrict__ out) {
    __shared__ float2 SW[WCAP];
    __shared__ int    sh_cnt[MAXSEG], sh_off[MAXSEG];
    __shared__ float  rf[NT / 32];
    __shared__ int    ri[NT / 32];
    __shared__ int    s_last;
    __shared__ double dsq[NT / 32], dbce[NT / 32], dsd[NT / 32], dsd2[NT / 32];
    __shared__ long long dcnt[NT / 32];

    const int tid = threadIdx.x;
    const int lane = tid & 31, w = tid >> 5;
    const int b = blockIdx.x / SPLITB;
    const int s = blockIdx.x % SPLITB;

    const int lo_b = max(b - 1, 0);
    const int hi_b = min(b + 2, NBUCK);
    const int nseg = (hi_b - lo_b) * NBLK1;

    if (tid < nseg) {
        int bw = lo_b + tid / NBLK1, sb = tid % NBLK1;
        sh_cnt[tid] = g_hist[bw * NBLK1 + sb];
    }
    __syncthreads();
    if (tid < nseg) {                 // exclusive prefix (small, deterministic)
        int o = 0;
        for (int k = 0; k < nseg; k++)
            if (k < tid) o += sh_cnt[k];
        sh_off[tid] = o;
    }
    __syncthreads();
    const int wn = sh_off[nseg - 1] + sh_cnt[nseg - 1];
    const bool use_s = (wn <= WCAP);

    if (use_s) {
        for (int seg = w; seg < nseg; seg += NT / 32) {
            int c = sh_cnt[seg], o = sh_off[seg];
            int bw = lo_b + seg / NBLK1, sb = seg % NBLK1;
            const float2* sp = &g_seg[(bw * NBLK1 + sb) * CAP];
            for (int k = lane; k < c; k += 32)
                SW[o + k] = sp[k];
        }
    }
    __syncthreads();

    // bucket-b region inside the window (the i-elements)
    const int idxs = (b - lo_b) * NBLK1;
    const int istart = sh_off[idxs];
    const int iend = (idxs + NBLK1 < nseg) ? sh_off[idxs + NBLK1] : wn;
    const int cnt_b = iend - istart;

    const int il = tid & 63;          // 64 i-lanes
    const int js = tid >> 6;          // 4 j-splits (uniform per warp)

    int nmine = (cnt_b > s) ? (cnt_b - s + SPLITB - 1) / SPLITB : 0;

    float sq = 0.0f;
    int cnt = 0;
    if (use_s) {
        for (int idx = il; idx < nmine; idx += 64) {
            int iloc = s + idx * SPLITB;
            float2 me = SW[istart + iloc];
            float pi = me.x, di = me.y;
#pragma unroll 4
            for (int k = js; k < wn; k += JSPLIT) {
                float2 v = SW[k];
                float ori = pi - v.x;
                float dv  = di - v.y;
                bool ok = fabsf(ori) < TH;
                float dvm = ok ? dv : 0.0f;      // FSEL, no branch
                sq = fmaf(dvm, dv, sq);
                cnt += ok ? 1 : 0;               // SEL+IADD, no branch
            }
        }
    } else {
        // fallback: scan directly from global segments (branchless too)
        for (int idx = il; idx < nmine; idx += 64) {
            int iloc = s + idx * SPLITB;
            int rem = iloc, seg = idxs;
            while (rem >= sh_cnt[seg]) { rem -= sh_cnt[seg]; seg++; }
            int bw = lo_b + seg / NBLK1, sb = seg % NBLK1;
            float2 me = g_seg[(bw * NBLK1 + sb) * CAP + rem];
            float pi = me.x, di = me.y;
            for (int sg = 0; sg < nseg; sg++) {
                int c = sh_cnt[sg];
                int bw2 = lo_b + sg / NBLK1, sb2 = sg % NBLK1;
                const float2* sp = &g_seg[(bw2 * NBLK1 + sb2) * CAP];
                for (int k = js; k < c; k += JSPLIT) {
                    float2 v = sp[k];
                    float ori = pi - v.x;
                    float dv  = di - v.y;
                    bool ok = fabsf(ori) < TH;
                    float dvm = ok ? dv : 0.0f;
                    sq = fmaf(dvm, dv, sq);
                    cnt += ok ? 1 : 0;
                }
            }
        }
    }

    float sv = warp_sum_f(sq);
    int cv = warp_sum_i(cnt);
    if (lane == 0) { rf[w] = sv; ri[w] = cv; }
    __syncthreads();
    if (tid == 0) {
        float av = 0; int ac = 0;
#pragma unroll
        for (int ww = 0; ww < NT / 32; ww++) { av += rf[ww]; ac += ri[ww]; }
        g_psq[blockIdx.x] = av;
        g_pcnt[blockIdx.x] = ac;
    }

    // ---- last-block ticket -> finalize ----
    if (tid == 0) {
        __threadfence();                          // release partials
        unsigned tk = atomicAdd(&g_done, 1u);
        s_last = (tk == NB2 - 1);
    }
    __syncthreads();
    if (!s_last) return;
    if (tid == 0) atomicExch(&g_done, 0u);        // reset for next replay
    __threadfence();                              // acquire all partials
    __syncthreads();

    {
        double psq = 0.0, bce = 0.0, sd = 0.0, sd2 = 0.0;
        long long pc = 0;
        for (int k = tid; k < NB2; k += NT) {
            psq += (double)g_psq[k];
            pc  += (long long)g_pcnt[k];
        }
        if (tid < NBLK1) {
            bce = (double)g_bce[tid];
            sd  = (double)g_sd[tid];
            sd2 = (double)g_sd2[tid];
        }
#pragma unroll
        for (int o = 16; o > 0; o >>= 1) {
            psq += __shfl_down_sync(0xffffffffu, psq, o);
            pc  += __shfl_down_sync(0xffffffffu, pc, o);
            bce += __shfl_down_sync(0xffffffffu, bce, o);
            sd  += __shfl_down_sync(0xffffffffu, sd, o);
            sd2 += __shfl_down_sync(0xffffffffu, sd2, o);
        }
        if (lane == 0) {
            dsq[w] = psq; dcnt[w] = pc; dbce[w] = bce; dsd[w] = sd; dsd2[w] = sd2;
        }
        __syncthreads();
        if (tid == 0) {
            double SQ = 0, B = 0, SD = 0, SD2 = 0; long long C = 0;
#pragma unroll
            for (int ww = 0; ww < NT / 32; ww++) {
                SQ += dsq[ww]; C += dcnt[ww]; B += dbce[ww];
                SD += dsd[ww]; SD2 += dsd2[ww];
            }
            // closed form over all pairs, minus invalid contribution
            double Sall = 2.0 * (double)N_ELEMS * SD2 - 2.0 * SD * SD;
            long long nvalid = (long long)N_ELEMS * (long long)N_ELEMS - C;
            float loss = (float)(B / (double)N_ELEMS);
            float res = loss;
            if (*flag == 0 && nvalid > 0) {
                double mse = (Sall - SQ) / (double)nvalid;
                res = loss + 10.0f * (float)mse;
            }
            out[0] = res;
        }
    }
}

extern "C" void kernel_launch(void* const* d_in, const int* in_sizes, int n_in,
                              void* d_out, int out_size) {
    const float* pred = (const float*)d_in[0];
    const float* psi  = (const float*)d_in[1];
    const int*   flag = (const int*)d_in[2];
    float* out = (float*)d_out;

    prep_scatter_kernel<<<NBLK1, NT>>>(pred, psi);
    pair_final_kernel<<<NB2, NT>>>(flag, out);
}

// round 14
// speedup vs baseline: 1.0927x; 1.0927x over previous
#include <cuda_runtime.h>

#define N_ELEMS 8192
#define NT 256
#define NBLK1 32                    // kernel-1 blocks (32 x 256 = 8192)
#define NBUCK 20
#define CAP 256                     // per-(bucket,block) segment capacity
#define TH 0.05f
#define SPLITB 14                   // i-splits per bucket in kernel 2
#define NB2 (NBUCK * SPLITB)        // 280 blocks
#define JSPLIT 8                    // one j-split per warp
#define WCAP 4096
#define MAXSEG 96                   // 3 buckets x 32 segments

// ---- scratch (__device__ globals; no allocation allowed) ----
__device__ float2 g_seg[NBUCK * NBLK1 * CAP];      // interleaved (psi, d)
__device__ int    g_hist[NBUCK * NBLK1];           // [bucket][block]
__device__ float  g_bce[NBLK1], g_sd[NBLK1], g_sd2[NBLK1];
__device__ float  g_psq[NB2];
__device__ int    g_pcnt[NB2];
__device__ unsigned g_done;                        // ticket; self-resets

__device__ __forceinline__ float warp_sum_f(float v) {
#pragma unroll
    for (int o = 16; o > 0; o >>= 1) v += __shfl_down_sync(0xffffffffu, v, o);
    return v;
}
__device__ __forceinline__ int warp_sum_i(int v) {
#pragma unroll
    for (int o = 16; o > 0; o >>= 1) v += __shfl_down_sync(0xffffffffu, v, o);
    return v;
}
__device__ __forceinline__ int bucket_of(float p) {
    int b = (int)(p * 20.0f);
    return b > (NBUCK - 1) ? (NBUCK - 1) : b;
}

// ---------------------------------------------------------------------------
// Kernel 1: prep + deterministic segmented bucket scatter + hist + O(N) sums
// ---------------------------------------------------------------------------
__global__ void __launch_bounds__(NT, 1)
prep_scatter_kernel(const float* __restrict__ pred,
                    const float* __restrict__ psi) {
    __shared__ int   wcnt[NT / 32][NBUCK];
    __shared__ float rf1[NT / 32], rf2[NT / 32], rf3[NT / 32];

    const int tid = threadIdx.x, blk = blockIdx.x;
    const int lane = tid & 31, w = tid >> 5;

    if (tid < (NT / 32) * NBUCK) ((int*)wcnt)[tid] = 0;
    __syncthreads();

    int i = blk * NT + tid;
    float x = pred[i];
    float t = psi[i];

    // stable BCE-with-logits term (fast math, err ~2^-22)
    float term = fmaxf(x, 0.0f) - x * t + __logf(1.0f + __expf(-fabsf(x)));
    // logit with clamp [eps, 1-eps]
    float p = fminf(fmaxf(t, 1e-7f), 1.0f - 1e-7f);
    float d = x - (__logf(p) - __logf(1.0f - p));

    int b = bucket_of(t);
    unsigned m = __match_any_sync(0xffffffffu, b);
    int lr = __popc(m & ((1u << lane) - 1u));
    if (lr == 0) wcnt[w][b] = __popc(m);
    __syncthreads();

    int rank = lr;
#pragma unroll
    for (int ww = 0; ww < NT / 32; ww++)
        if (ww < w) rank += wcnt[ww][b];

    g_seg[(b * NBLK1 + blk) * CAP + rank] = make_float2(t, d);

    if (tid < NBUCK) {
        int s = 0;
#pragma unroll
        for (int ww = 0; ww < NT / 32; ww++) s += wcnt[ww][tid];
        g_hist[tid * NBLK1 + blk] = s;
    }

    float s1 = warp_sum_f(term);
    float s2 = warp_sum_f(d);
    float s3 = warp_sum_f(d * d);
    if (lane == 0) { rf1[w] = s1; rf2[w] = s2; rf3[w] = s3; }
    __syncthreads();
    if (tid == 0) {
        float a1 = 0, a2 = 0, a3 = 0;
#pragma unroll
        for (int ww = 0; ww < NT / 32; ww++) { a1 += rf1[ww]; a2 += rf2[ww]; a3 += rf3[ww]; }
        g_bce[blk] = a1; g_sd[blk] = a2; g_sd2[blk] = a3;
    }
}

// ---------------------------------------------------------------------------
// Kernel 2: gather 3-bucket window -> smem (float2), balanced branchless
// invalid-pair scan (all 8 warps work, 2 accumulators), ticket finalize.
// ---------------------------------------------------------------------------
__global__ void __launch_bounds__(NT, 2)
pair_final_kernel(const int* __restrict__ flag, float* __restrict__ out) {
    __shared__ float2 SW[WCAP];
    __shared__ int    sh_cnt[MAXSEG], sh_off[MAXSEG];
    __shared__ float  rf[NT / 32];
    __shared__ int    ri[NT / 32];
    __shared__ int    s_last;
    __shared__ double dsq[NT / 32], dbce[NT / 32], dsd[NT / 32], dsd2[NT / 32];
    __shared__ long long dcnt[NT / 32];

    const int tid = threadIdx.x;
    const int lane = tid & 31, w = tid >> 5;
    const int b = blockIdx.x / SPLITB;
    const int s = blockIdx.x % SPLITB;

    const int lo_b = max(b - 1, 0);
    const int hi_b = min(b + 2, NBUCK);
    const int nseg = (hi_b - lo_b) * NBLK1;

    if (tid < nseg) {
        int bw = lo_b + tid / NBLK1, sb = tid % NBLK1;
        sh_cnt[tid] = g_hist[bw * NBLK1 + sb];
    }
    __syncthreads();
    if (tid < nseg) {                 // exclusive prefix (small, deterministic)
        int o = 0;
        for (int k = 0; k < nseg; k++)
            if (k < tid) o += sh_cnt[k];
        sh_off[tid] = o;
    }
    __syncthreads();
    const int wn = sh_off[nseg - 1] + sh_cnt[nseg - 1];
    const bool use_s = (wn <= WCAP);

    if (use_s) {
        for (int seg = w; seg < nseg; seg += NT / 32) {
            int c = sh_cnt[seg], o = sh_off[seg];
            int bw = lo_b + seg / NBLK1, sb = seg % NBLK1;
            const float2* sp = &g_seg[(bw * NBLK1 + sb) * CAP];
            for (int k = lane; k < c; k += 32)
                SW[o + k] = sp[k];
        }
    }
    __syncthreads();

    // bucket-b region inside the window (the i-elements)
    const int idxs = (b - lo_b) * NBLK1;
    const int istart = sh_off[idxs];
    const int iend = (idxs + NBLK1 < nseg) ? sh_off[idxs + NBLK1] : wn;
    const int cnt_b = iend - istart;

    const int il = lane;              // 32 i-lanes (every warp participates)
    const int js = w;                 // 8 j-splits, one per warp

    int nmine = (cnt_b > s) ? (cnt_b - s + SPLITB - 1) / SPLITB : 0;

    float sq0 = 0.0f, sq1 = 0.0f;
    int cnt0 = 0, cnt1 = 0;
    if (use_s) {
        for (int idx = il; idx < nmine; idx += 32) {
            int iloc = s + idx * SPLITB;
            float2 me = SW[istart + iloc];
            float pi = me.x, di = me.y;
            int k = js;
            // 2-way unrolled, independent accumulators (breaks FFMA chain)
            for (; k + JSPLIT < wn; k += 2 * JSPLIT) {
                float2 v0 = SW[k];
                float2 v1 = SW[k + JSPLIT];
                float o0 = pi - v0.x, d0 = di - v0.y;
                float o1 = pi - v1.x, d1 = di - v1.y;
                bool k0 = fabsf(o0) < TH;
                bool k1 = fabsf(o1) < TH;
                sq0 = fmaf(k0 ? d0 : 0.0f, d0, sq0);
                sq1 = fmaf(k1 ? d1 : 0.0f, d1, sq1);
                cnt0 += k0 ? 1 : 0;
                cnt1 += k1 ? 1 : 0;
            }
            if (k < wn) {
                float2 v0 = SW[k];
                float o0 = pi - v0.x, d0 = di - v0.y;
                bool k0 = fabsf(o0) < TH;
                sq0 = fmaf(k0 ? d0 : 0.0f, d0, sq0);
                cnt0 += k0 ? 1 : 0;
            }
        }
    } else {
        // fallback: scan directly from global segments (branchless too)
        for (int idx = il; idx < nmine; idx += 32) {
            int iloc = s + idx * SPLITB;
            int rem = iloc, seg = idxs;
            while (rem >= sh_cnt[seg]) { rem -= sh_cnt[seg]; seg++; }
            int bw = lo_b + seg / NBLK1, sb = seg % NBLK1;
            float2 me = g_seg[(bw * NBLK1 + sb) * CAP + rem];
            float pi = me.x, di = me.y;
            for (int sg = 0; sg < nseg; sg++) {
                int c = sh_cnt[sg];
                int bw2 = lo_b + sg / NBLK1, sb2 = sg % NBLK1;
                const float2* sp = &g_seg[(bw2 * NBLK1 + sb2) * CAP];
                for (int k = js; k < c; k += JSPLIT) {
                    float2 v = sp[k];
                    float ori = pi - v.x;
                    float dv  = di - v.y;
                    bool ok = fabsf(ori) < TH;
                    sq0 = fmaf(ok ? dv : 0.0f, dv, sq0);
                    cnt0 += ok ? 1 : 0;
                }
            }
        }
    }

    float sv = warp_sum_f(sq0 + sq1);
    int cv = warp_sum_i(cnt0 + cnt1);
    if (lane == 0) { rf[w] = sv; ri[w] = cv; }
    __syncthreads();
    if (tid == 0) {
        float av = 0; int ac = 0;
#pragma unroll
        for (int ww = 0; ww < NT / 32; ww++) { av += rf[ww]; ac += ri[ww]; }
        g_psq[blockIdx.x] = av;
        g_pcnt[blockIdx.x] = ac;
    }

    // ---- last-block ticket -> finalize ----
    if (tid == 0) {
        __threadfence();                          // release partials
        unsigned tk = atomicAdd(&g_done, 1u);
        s_last = (tk == NB2 - 1);
    }
    __syncthreads();
    if (!s_last) return;
    if (tid == 0) atomicExch(&g_done, 0u);        // reset for next replay
    __threadfence();                              // acquire all partials
    __syncthreads();

    {
        double psq = 0.0, bce = 0.0, sd = 0.0, sd2 = 0.0;
        long long pc = 0;
        for (int k = tid; k < NB2; k += NT) {
            psq += (double)g_psq[k];
            pc  += (long long)g_pcnt[k];
        }
        if (tid < NBLK1) {
            bce = (double)g_bce[tid];
            sd  = (double)g_sd[tid];
            sd2 = (double)g_sd2[tid];
        }
#pragma unroll
        for (int o = 16; o > 0; o >>= 1) {
            psq += __shfl_down_sync(0xffffffffu, psq, o);
            pc  += __shfl_down_sync(0xffffffffu, pc, o);
            bce += __shfl_down_sync(0xffffffffu, bce, o);
            sd  += __shfl_down_sync(0xffffffffu, sd, o);
            sd2 += __shfl_down_sync(0xffffffffu, sd2, o);
        }
        if (lane == 0) {
            dsq[w] = psq; dcnt[w] = pc; dbce[w] = bce; dsd[w] = sd; dsd2[w] = sd2;
        }
        __syncthreads();
        if (tid == 0) {
            double SQ = 0, B = 0, SD = 0, SD2 = 0; long long C = 0;
#pragma unroll
            for (int ww = 0; ww < NT / 32; ww++) {
                SQ += dsq[ww]; C += dcnt[ww]; B += dbce[ww];
                SD += dsd[ww]; SD2 += dsd2[ww];
            }
            // closed form over all pairs, minus invalid contribution
            double Sall = 2.0 * (double)N_ELEMS * SD2 - 2.0 * SD * SD;
            long long nvalid = (long long)N_ELEMS * (long long)N_ELEMS - C;
            float loss = (float)(B / (double)N_ELEMS);
            float res = loss;
            if (*flag == 0 && nvalid > 0) {
                double mse = (Sall - SQ) / (double)nvalid;
                res = loss + 10.0f * (float)mse;
            }
            out[0] = res;
        }
    }
}

extern "C" void kernel_launch(void* const* d_in, const int* in_sizes, int n_in,
                              void* d_out, int out_size) {
    const float* pred = (const float*)d_in[0];
    const float* psi  = (const float*)d_in[1];
    const int*   flag = (const int*)d_in[2];
    float* out = (float*)d_out;

    prep_scatter_kernel<<<NBLK1, NT>>>(pred, psi);
    pair_final_kernel<<<NB2, NT>>>(flag, out);
}

// round 15
// speedup vs baseline: 1.0977x; 1.0046x over previous
#include <cuda_runtime.h>

#define N_ELEMS 8192
#define NT 256
#define NBLK1 32                    // kernel-1 blocks (32 x 256 = 8192)
#define NBUCK 20
#define CAP 256                     // per-(bucket,block) segment capacity
#define TH 0.05f
#define SPLITB 7                    // i-splits per bucket in kernel 2
#define NB2 (NBUCK * SPLITB)        // 140 blocks = 1 per SM
#define JSPLIT 8                    // one j-split per warp
#define WCAP 4096
#define MAXSEG 96                   // 3 buckets x 32 segments

// ---- scratch (__device__ globals; no allocation allowed) ----
__device__ float2 g_seg[NBUCK * NBLK1 * CAP];      // interleaved (psi, d)
__device__ int    g_hist[NBUCK * NBLK1];           // [bucket][block]
__device__ float  g_bce[NBLK1], g_sd[NBLK1], g_sd2[NBLK1];
__device__ float  g_psq[NB2];
__device__ int    g_pcnt[NB2];
__device__ unsigned g_done;                        // ticket; self-resets

__device__ __forceinline__ float warp_sum_f(float v) {
#pragma unroll
    for (int o = 16; o > 0; o >>= 1) v += __shfl_down_sync(0xffffffffu, v, o);
    return v;
}
__device__ __forceinline__ int warp_sum_i(int v) {
#pragma unroll
    for (int o = 16; o > 0; o >>= 1) v += __shfl_down_sync(0xffffffffu, v, o);
    return v;
}
__device__ __forceinline__ int bucket_of(float p) {
    int b = (int)(p * 20.0f);
    return b > (NBUCK - 1) ? (NBUCK - 1) : b;
}

// ---------------------------------------------------------------------------
// Kernel 1: prep + deterministic segmented bucket scatter + hist + O(N) sums
// ---------------------------------------------------------------------------
__global__ void __launch_bounds__(NT, 1)
prep_scatter_kernel(const float* __restrict__ pred,
                    const float* __restrict__ psi) {
    __shared__ int   wcnt[NT / 32][NBUCK];
    __shared__ float rf1[NT / 32], rf2[NT / 32], rf3[NT / 32];

    const int tid = threadIdx.x, blk = blockIdx.x;
    const int lane = tid & 31, w = tid >> 5;

    if (tid < (NT / 32) * NBUCK) ((int*)wcnt)[tid] = 0;
    __syncthreads();

    int i = blk * NT + tid;
    float x = pred[i];
    float t = psi[i];

    // stable BCE-with-logits term (fast math, err ~2^-22)
    float term = fmaxf(x, 0.0f) - x * t + __logf(1.0f + __expf(-fabsf(x)));
    // logit with clamp [eps, 1-eps]
    float p = fminf(fmaxf(t, 1e-7f), 1.0f - 1e-7f);
    float d = x - (__logf(p) - __logf(1.0f - p));

    int b = bucket_of(t);
    unsigned m = __match_any_sync(0xffffffffu, b);
    int lr = __popc(m & ((1u << lane) - 1u));
    if (lr == 0) wcnt[w][b] = __popc(m);
    __syncthreads();

    int rank = lr;
#pragma unroll
    for (int ww = 0; ww < NT / 32; ww++)
        if (ww < w) rank += wcnt[ww][b];

    g_seg[(b * NBLK1 + blk) * CAP + rank] = make_float2(t, d);

    if (tid < NBUCK) {
        int s = 0;
#pragma unroll
        for (int ww = 0; ww < NT / 32; ww++) s += wcnt[ww][tid];
        g_hist[tid * NBLK1 + blk] = s;
    }

    float s1 = warp_sum_f(term);
    float s2 = warp_sum_f(d);
    float s3 = warp_sum_f(d * d);
    if (lane == 0) { rf1[w] = s1; rf2[w] = s2; rf3[w] = s3; }
    __syncthreads();
    if (tid == 0) {
        float a1 = 0, a2 = 0, a3 = 0;
#pragma unroll
        for (int ww = 0; ww < NT / 32; ww++) { a1 += rf1[ww]; a2 += rf2[ww]; a3 += rf3[ww]; }
        g_bce[blk] = a1; g_sd[blk] = a2; g_sd2[blk] = a3;
    }
}

// ---------------------------------------------------------------------------
// Kernel 2: gather window -> smem, i-register-tiled (IT=2) branchless scan,
// one LDS.64 feeds 12 independent compute issues. Ticket finalize.
// ---------------------------------------------------------------------------
__global__ void __launch_bounds__(NT, 1)
pair_final_kernel(const int* __restrict__ flag, float* __restrict__ out) {
    __shared__ float2 SW[WCAP];
    __shared__ int    sh_cnt[MAXSEG], sh_off[MAXSEG];
    __shared__ float  rf[NT / 32];
    __shared__ int    ri[NT / 32];
    __shared__ int    s_last;
    __shared__ double dsq[NT / 32], dbce[NT / 32], dsd[NT / 32], dsd2[NT / 32];
    __shared__ long long dcnt[NT / 32];

    const int tid = threadIdx.x;
    const int lane = tid & 31, w = tid >> 5;
    const int b = blockIdx.x / SPLITB;
    const int s = blockIdx.x % SPLITB;

    const int lo_b = max(b - 1, 0);
    const int hi_b = min(b + 2, NBUCK);
    const int nseg = (hi_b - lo_b) * NBLK1;

    if (tid < nseg) {
        int bw = lo_b + tid / NBLK1, sb = tid % NBLK1;
        sh_cnt[tid] = g_hist[bw * NBLK1 + sb];
    }
    __syncthreads();
    if (tid < nseg) {                 // exclusive prefix (small, deterministic)
        int o = 0;
        for (int k = 0; k < nseg; k++)
            if (k < tid) o += sh_cnt[k];
        sh_off[tid] = o;
    }
    __syncthreads();
    const int wn = sh_off[nseg - 1] + sh_cnt[nseg - 1];
    const bool use_s = (wn <= WCAP);

    if (use_s) {
        for (int seg = w; seg < nseg; seg += NT / 32) {
            int c = sh_cnt[seg], o = sh_off[seg];
            int bw = lo_b + seg / NBLK1, sb = seg % NBLK1;
            const float2* sp = &g_seg[(bw * NBLK1 + sb) * CAP];
            for (int k = lane; k < c; k += 32)
                SW[o + k] = sp[k];
        }
    }
    __syncthreads();

    // bucket-b region inside the window (the i-elements)
    const int idxs = (b - lo_b) * NBLK1;
    const int istart = sh_off[idxs];
    const int iend = (idxs + NBLK1 < nseg) ? sh_off[idxs + NBLK1] : wn;
    const int cnt_b = iend - istart;

    // i's owned by this block: local indices s, s+7, s+14, ...
    const int nmine = (cnt_b > s) ? (cnt_b - s + SPLITB - 1) / SPLITB : 0;

    float sq0 = 0.0f, sq1 = 0.0f;
    int cnt0 = 0, cnt1 = 0;

    if (use_s) {
        // chunks of 64 slots: slot0 = base+lane, slot1 = base+lane+32
        for (int base = 0; base < nmine; base += 64) {
            int sl0 = base + lane;
            int sl1 = base + lane + 32;
            bool v0 = sl0 < nmine;
            bool v1 = sl1 < nmine;
            // ghost i: psi=3.0 can never be within TH of window psi in [0,1)
            float pi0 = 3.0f, di0 = 0.0f, pi1 = 3.0f, di1 = 0.0f;
            if (v0) { float2 m0 = SW[istart + s + sl0 * SPLITB]; pi0 = m0.x; di0 = m0.y; }
            if (v1) { float2 m1 = SW[istart + s + sl1 * SPLITB]; pi1 = m1.x; di1 = m1.y; }

            // j sweep: warp w takes k = w, w+8, w+16, ...
#pragma unroll 2
            for (int k = w; k < wn; k += JSPLIT) {
                float2 v = SW[k];                 // one LDS.64, two i's use it
                float o0 = pi0 - v.x, e0 = di0 - v.y;
                float o1 = pi1 - v.x, e1 = di1 - v.y;
                bool k0 = fabsf(o0) < TH;
                bool k1 = fabsf(o1) < TH;
                sq0 = fmaf(k0 ? e0 : 0.0f, e0, sq0);
                sq1 = fmaf(k1 ? e1 : 0.0f, e1, sq1);
                cnt0 += k0 ? 1 : 0;
                cnt1 += k1 ? 1 : 0;
            }
        }
    } else {
        // rare fallback: scan directly from global segments
        for (int idx = lane; idx < nmine; idx += 32) {
            int iloc = s + idx * SPLITB;
            int rem = iloc, seg = idxs;
            while (rem >= sh_cnt[seg]) { rem -= sh_cnt[seg]; seg++; }
            int bw = lo_b + seg / NBLK1, sb = seg % NBLK1;
            float2 me = g_seg[(bw * NBLK1 + sb) * CAP + rem];
            float pi = me.x, di = me.y;
            for (int sg = 0; sg < nseg; sg++) {
                int c = sh_cnt[sg];
                int bw2 = lo_b + sg / NBLK1, sb2 = sg % NBLK1;
                const float2* sp = &g_seg[(bw2 * NBLK1 + sb2) * CAP];
                for (int k = w; k < c; k += JSPLIT) {
                    float2 v = sp[k];
                    float ori = pi - v.x;
                    float dv  = di - v.y;
                    bool ok = fabsf(ori) < TH;
                    sq0 = fmaf(ok ? dv : 0.0f, dv, sq0);
                    cnt0 += ok ? 1 : 0;
                }
            }
        }
    }

    float sv = warp_sum_f(sq0 + sq1);
    int cv = warp_sum_i(cnt0 + cnt1);
    if (lane == 0) { rf[w] = sv; ri[w] = cv; }
    __syncthreads();
    if (tid == 0) {
        float av = 0; int ac = 0;
#pragma unroll
        for (int ww = 0; ww < NT / 32; ww++) { av += rf[ww]; ac += ri[ww]; }
        g_psq[blockIdx.x] = av;
        g_pcnt[blockIdx.x] = ac;
    }

    // ---- last-block ticket -> finalize ----
    if (tid == 0) {
        __threadfence();                          // release partials
        unsigned tk = atomicAdd(&g_done, 1u);
        s_last = (tk == NB2 - 1);
    }
    __syncthreads();
    if (!s_last) return;
    if (tid == 0) atomicExch(&g_done, 0u);        // reset for next replay
    __threadfence();                              // acquire all partials
    __syncthreads();

    {
        double psq = 0.0, bce = 0.0, sd = 0.0, sd2 = 0.0;
        long long pc = 0;
        for (int k = tid; k < NB2; k += NT) {
            psq += (double)g_psq[k];
            pc  += (long long)g_pcnt[k];
        }
        if (tid < NBLK1) {
            bce = (double)g_bce[tid];
            sd  = (double)g_sd[tid];
            sd2 = (double)g_sd2[tid];
        }
#pragma unroll
        for (int o = 16; o > 0; o >>= 1) {
            psq += __shfl_down_sync(0xffffffffu, psq, o);
            pc  += __shfl_down_sync(0xffffffffu, pc, o);
            bce += __shfl_down_sync(0xffffffffu, bce, o);
            sd  += __shfl_down_sync(0xffffffffu, sd, o);
            sd2 += __shfl_down_sync(0xffffffffu, sd2, o);
        }
        if (lane == 0) {
            dsq[w] = psq; dcnt[w] = pc; dbce[w] = bce; dsd[w] = sd; dsd2[w] = sd2;
        }
        __syncthreads();
        if (tid == 0) {
            double SQ = 0, B = 0, SD = 0, SD2 = 0; long long C = 0;
#pragma unroll
            for (int ww = 0; ww < NT / 32; ww++) {
                SQ += dsq[ww]; C += dcnt[ww]; B += dbce[ww];
                SD += dsd[ww]; SD2 += dsd2[ww];
            }
            // closed form over all pairs, minus invalid contribution
            double Sall = 2.0 * (double)N_ELEMS * SD2 - 2.0 * SD * SD;
            long long nvalid = (long long)N_ELEMS * (long long)N_ELEMS - C;
            float loss = (float)(B / (double)N_ELEMS);
            float res = loss;
            if (*flag == 0 && nvalid > 0) {
                double mse = (Sall - SQ) / (double)nvalid;
                res = loss + 10.0f * (float)mse;
            }
            out[0] = res;
        }
    }
}

extern "C" void kernel_launch(void* const* d_in, const int* in_sizes, int n_in,
                              void* d_out, int out_size) {
    const float* pred = (const float*)d_in[0];
    const float* psi  = (const float*)d_in[1];
    const int*   flag = (const int*)d_in[2];
    float* out = (float*)d_out;

    prep_scatter_kernel<<<NBLK1, NT>>>(pred, psi);
    pair_final_kernel<<<NB2, NT>>>(flag, out);
}